// round 17
// baseline (speedup 1.0000x reference)
#include <cuda_runtime.h>
#include <cuda_fp16.h>
#include <cstdint>

#define F_IN 256
#define F_OUT 64
#define MAX_N 100000
#define MAX_E 3200000

// gemm smem: Xs[2][128][36] + Ws[2][32][64] floats
#define XS_ROW 36
#define SMEM_GEMM ((2*128*XS_ROW + 2*32*64) * 4)

// Scratch (device globals — no allocation allowed)
__device__ __half g_h16[(size_t)MAX_N * F_OUT];
__device__ float  g_s1[MAX_N];
__device__ float  g_s2[MAX_N];
__device__ int    g_deg[MAX_N];
__device__ int    g_rowptr[MAX_N + 1];   // [i+1] = LOCAL inclusive scan of deg
__device__ int    g_rank[MAX_E];
__device__ int    g_sdst[MAX_E];
__device__ int    g_bsum[128];           // exclusive-scanned block sums
__device__ int    g_scan_ctr;
__device__ int    g_is64;

// rowbase(i): global exclusive prefix = local inclusive(i-1) + block offset
__device__ __forceinline__ int rowbase(int i) {
    return (i == 0) ? 0 : g_rowptr[i] + g_bsum[(i - 1) >> 10];
}

// ---------------------------------------------------------------------------
// init: detect edge dtype (block 0 warp 0), zero deg, zero scan counter
// ---------------------------------------------------------------------------
__global__ void init_kernel(const int* __restrict__ ei32, int M) {
    if (blockIdx.x == 0 && threadIdx.x < 32) {
        int lane = threadIdx.x;
        int bad = 0;
        for (int i = lane; i < 64; i += 32)
            if (ei32[2 * i + 1] != 0) bad = 1;
        unsigned m = __ballot_sync(0xffffffffu, bad);
        if (lane == 0) { g_is64 = (m == 0u); g_scan_ctr = 0; }
    }
    int i = blockIdx.x * blockDim.x + threadIdx.x;
    if (i < M) g_deg[i] = 0;
}

__device__ __forceinline__ int edge_at(const int* ei32, int is64, long long idx) {
    return is64 ? ei32[2 * idx] : ei32[idx];   // little-endian low word
}

// ---------------------------------------------------------------------------
// Packed f32x2 helpers (sm_100+ PTX; ptxas never auto-fuses FFMA2)
// ---------------------------------------------------------------------------
__device__ __forceinline__ unsigned long long pack_dup(float x) {
    unsigned long long r;
    unsigned u = __float_as_uint(x);
    asm("mov.b64 %0, {%1, %1};" : "=l"(r) : "r"(u));
    return r;
}
__device__ __forceinline__ unsigned long long pack2(float x, float y) {
    unsigned long long r;
    asm("mov.b64 %0, {%1, %2};" : "=l"(r) : "f"(x), "f"(y));
    return r;
}
__device__ __forceinline__ void fma_f32x2(unsigned long long& acc,
                                          unsigned long long a,
                                          unsigned long long b) {
    asm("fma.rn.f32x2 %0, %1, %2, %0;" : "+l"(acc) : "l"(a), "l"(b));
}

__device__ __forceinline__ uint32_t smem_u32(const void* p) {
    uint32_t r;
    asm("{ .reg .u64 t; cvta.to.shared.u64 t, %1; cvt.u32.u64 %0, t; }" : "=r"(r) : "l"(p));
    return r;
}

// ---------------------------------------------------------------------------
// GEMM: 128x64 tile, f32x2 8x4 thread tile, cp.async DOUBLE-BUFFERED staging
// (copy of chunk c+1 overlaps compute of chunk c). Fused s1/s2 epilogue.
// ---------------------------------------------------------------------------
__global__ __launch_bounds__(256) void gemm_kernel(
    const float* __restrict__ X, const float* __restrict__ W,
    const float* __restrict__ a, int M)
{
    extern __shared__ __align__(16) float sm[];
    float* Xs = sm;                             // [2][128][XS_ROW]
    float* Ws = sm + 2 * 128 * XS_ROW;          // [2][32][64]
    uint32_t sbase = smem_u32(sm);
    const uint32_t WsB = 2u * 128 * XS_ROW * 4; // byte offset of Ws

    int tid = threadIdx.x;
    int tx = tid & 15;   // col group: cols tx*4 .. tx*4+3
    int ty = tid >> 4;   // row group: rows ty*8 .. ty*8+7
    int m0 = blockIdx.x * 128;

    unsigned long long accp[4][4];
#pragma unroll
    for (int p = 0; p < 4; p++)
#pragma unroll
        for (int j = 0; j < 4; j++) accp[p][j] = 0ull;

    // per-thread staging assignments
    int xr = (tid >> 3);          // base row  (with +32 per i)
    int xkc = (tid & 7) * 4;      // float col within chunk
    int wkr = (tid >> 4);         // W row (with +16 per i)
    int wc4 = (tid & 15) * 4;

    auto issue_chunk = [&](int k0, int buf) {
#pragma unroll
        for (int i = 0; i < 4; i++) {
            int r = xr + i * 32;
            int row = m0 + r;
            const float* src = X + (size_t)row * F_IN + k0 + xkc;
            uint32_t dst = sbase + (uint32_t)(((buf * 128 + r) * XS_ROW + xkc) * 4);
            int bytes = (row < M) ? 16 : 0;
            asm volatile("cp.async.cg.shared.global [%0], [%1], 16, %2;"
                         :: "r"(dst), "l"(src), "r"(bytes) : "memory");
        }
#pragma unroll
        for (int i = 0; i < 2; i++) {
            int kr = wkr + i * 16;
            const float* src = W + (size_t)(k0 + kr) * F_OUT + wc4;
            uint32_t dst = sbase + WsB + (uint32_t)(((buf * 32 + kr) * 64 + wc4) * 4);
            asm volatile("cp.async.cg.shared.global [%0], [%1], 16;"
                         :: "r"(dst), "l"(src) : "memory");
        }
        asm volatile("cp.async.commit_group;" ::: "memory");
    };

    issue_chunk(0, 0);

    for (int c = 0; c < 8; c++) {
        asm volatile("cp.async.wait_group 0;" ::: "memory");
        __syncthreads();                 // chunk c visible to all; prev compute done
        if (c < 7) issue_chunk((c + 1) * 32, (c + 1) & 1);

        const float* Xb = Xs + (c & 1) * 128 * XS_ROW;
        const float* Wb = Ws + (c & 1) * 32 * 64;
#pragma unroll
        for (int kk = 0; kk < 32; kk++) {
            float4 b = *(const float4*)&Wb[kk * 64 + tx * 4];
            unsigned long long bv0 = pack_dup(b.x);
            unsigned long long bv1 = pack_dup(b.y);
            unsigned long long bv2 = pack_dup(b.z);
            unsigned long long bv3 = pack_dup(b.w);
            unsigned long long av[4];
#pragma unroll
            for (int p = 0; p < 4; p++) {
                float x0 = Xb[(ty * 8 + 2 * p) * XS_ROW + kk];
                float x1 = Xb[(ty * 8 + 2 * p + 1) * XS_ROW + kk];
                av[p] = pack2(x0, x1);
            }
#pragma unroll
            for (int p = 0; p < 4; p++) {
                fma_f32x2(accp[p][0], av[p], bv0);
                fma_f32x2(accp[p][1], av[p], bv1);
                fma_f32x2(accp[p][2], av[p], bv2);
                fma_f32x2(accp[p][3], av[p], bv3);
            }
        }
    }

    float accf[8][4];
#pragma unroll
    for (int p = 0; p < 4; p++)
#pragma unroll
        for (int j = 0; j < 4; j++) {
            float2 f = *reinterpret_cast<float2*>(&accp[p][j]);
            accf[2 * p][j]     = f.x;
            accf[2 * p + 1][j] = f.y;
        }

    // Store h as fp16
#pragma unroll
    for (int i = 0; i < 8; i++) {
        int row = m0 + ty * 8 + i;
        if (row < M) {
            __half2 lo = __floats2half2_rn(accf[i][0], accf[i][1]);
            __half2 hi = __floats2half2_rn(accf[i][2], accf[i][3]);
            uint2 pkt = make_uint2(*(unsigned*)&lo, *(unsigned*)&hi);
            *(uint2*)(g_h16 + (size_t)row * F_OUT + tx * 4) = pkt;
        }
    }

    // Fused s1/s2 epilogue (fp32, exact)
    float a1v[4], a2v[4];
#pragma unroll
    for (int j = 0; j < 4; j++) {
        a1v[j] = __ldg(a + tx * 4 + j);
        a2v[j] = __ldg(a + 64 + tx * 4 + j);
    }
    float s1p[8], s2p[8];
#pragma unroll
    for (int i = 0; i < 8; i++) {
        float t1 = 0.f, t2 = 0.f;
#pragma unroll
        for (int j = 0; j < 4; j++) {
            t1 = fmaf(accf[i][j], a1v[j], t1);
            t2 = fmaf(accf[i][j], a2v[j], t2);
        }
        s1p[i] = t1; s2p[i] = t2;
    }
#pragma unroll
    for (int o = 1; o < 16; o <<= 1) {
#pragma unroll
        for (int i = 0; i < 8; i++) {
            s1p[i] += __shfl_xor_sync(0xffffffffu, s1p[i], o);
            s2p[i] += __shfl_xor_sync(0xffffffffu, s2p[i], o);
        }
    }
    if (tx == 0) {
#pragma unroll
        for (int i = 0; i < 8; i++) {
            int row = m0 + ty * 8 + i;
            if (row < M) { g_s1[row] = s1p[i]; g_s2[row] = s2p[i]; }
        }
    }
}

// ---------------------------------------------------------------------------
// rank pass: per-edge position within its src bucket (one atomic pass)
// ---------------------------------------------------------------------------
__global__ void rank_kernel(const int* __restrict__ ei32, int E, int M) {
    int e = blockIdx.x * blockDim.x + threadIdx.x;
    if (e >= E) return;
    int is64 = g_is64;
    int src = edge_at(ei32, is64, e);
    int dst = edge_at(ei32, is64, (long long)E + e);
    int r = -1;
    if ((unsigned)src < (unsigned)M && (unsigned)dst < (unsigned)M)
        r = atomicAdd(&g_deg[src], 1);
    g_rank[e] = r;
}

// ---------------------------------------------------------------------------
// Fused scan: per-1024-block local inclusive scan; the LAST block to finish
// also exclusive-scans the (<=128) block sums in place (threadfence+counter).
// ---------------------------------------------------------------------------
__global__ void scan_kernel(int n, int nblk) {
    __shared__ int s[1024];
    __shared__ int isLast;
    int i = blockIdx.x * 1024 + threadIdx.x;
    int v = (i < n) ? g_deg[i] : 0;
    s[threadIdx.x] = v;
    __syncthreads();
#pragma unroll
    for (int o = 1; o < 1024; o <<= 1) {
        int t = (threadIdx.x >= o) ? s[threadIdx.x - o] : 0;
        __syncthreads();
        s[threadIdx.x] += t;
        __syncthreads();
    }
    if (i < n) g_rowptr[i + 1] = s[threadIdx.x];
    if (threadIdx.x == 1023) {
        g_bsum[blockIdx.x] = s[1023];
        __threadfence();
        int prev = atomicAdd(&g_scan_ctr, 1);
        isLast = (prev == nblk - 1);
    }
    __syncthreads();
    if (isLast) {
        __threadfence();   // acquire all blocks' bsum writes
        int bv = (threadIdx.x < nblk) ? g_bsum[threadIdx.x] : 0;
        if (threadIdx.x < 128) s[threadIdx.x] = bv;
        __syncthreads();
#pragma unroll
        for (int o = 1; o < 128; o <<= 1) {
            int t = (threadIdx.x < 128 && threadIdx.x >= o) ? s[threadIdx.x - o] : 0;
            __syncthreads();
            if (threadIdx.x < 128) s[threadIdx.x] += t;
            __syncthreads();
        }
        if (threadIdx.x < nblk) g_bsum[threadIdx.x] = s[threadIdx.x] - bv;
    }
}

// ---------------------------------------------------------------------------
// Scatter: atomic-free using precomputed ranks; rowptr via rowbase() inline
// ---------------------------------------------------------------------------
__global__ void scatter_kernel(const int* __restrict__ ei32, int E, int M) {
    int e = blockIdx.x * blockDim.x + threadIdx.x;
    if (e >= E) return;
    int r = g_rank[e];
    if (r < 0) return;
    int is64 = g_is64;
    int src = edge_at(ei32, is64, e);
    int dst = edge_at(ei32, is64, (long long)E + e);
    g_sdst[rowbase(src) + r] = dst;
}

// ---------------------------------------------------------------------------
// Aggregate + finalize (R7 form, frozen): one warp per node, 4 edge-groups x
// 8 lanes x 8 feats, prefetch next sdst. Fused rowsum-divide + ELU.
// w = exp(lrelu(s1[src]+s2[dst]))   (global-max subtraction cancels; skipped)
// ---------------------------------------------------------------------------
__global__ void aggregate_kernel(float* __restrict__ out, int M) {
    int node = (blockIdx.x * blockDim.x + threadIdx.x) >> 5;
    if (node >= M) return;
    int lane = threadIdx.x & 31;
    int sub  = lane & 7;
    int eg   = lane >> 3;

    int beg = rowbase(node);
    int end = rowbase(node + 1);
    float s1v = g_s1[node];

    float acc[8];
#pragma unroll
    for (int j = 0; j < 8; j++) acc[j] = 0.0f;
    float wsum = 0.0f;

    int p = beg + eg;
    int dst_cur = (p < end) ? g_sdst[p] : 0;
    for (; p < end; p += 4) {
        int pn = p + 4;
        int dst_next = (pn < end) ? g_sdst[pn] : 0;   // prefetch

        float s2v = g_s2[dst_cur];
        uint4 q = *(const uint4*)(g_h16 + (size_t)dst_cur * F_OUT + sub * 8);

        float v  = s1v + s2v;
        float ev = v > 0.0f ? v : 0.2f * v;
        float w  = __expf(ev);
        wsum += w;

        float2 f0 = __half22float2(*(const __half2*)&q.x);
        float2 f1 = __half22float2(*(const __half2*)&q.y);
        float2 f2 = __half22float2(*(const __half2*)&q.z);
        float2 f3 = __half22float2(*(const __half2*)&q.w);
        acc[0] = fmaf(w, f0.x, acc[0]);
        acc[1] = fmaf(w, f0.y, acc[1]);
        acc[2] = fmaf(w, f1.x, acc[2]);
        acc[3] = fmaf(w, f1.y, acc[3]);
        acc[4] = fmaf(w, f2.x, acc[4]);
        acc[5] = fmaf(w, f2.y, acc[5]);
        acc[6] = fmaf(w, f3.x, acc[6]);
        acc[7] = fmaf(w, f3.y, acc[7]);

        dst_cur = dst_next;
    }

#pragma unroll
    for (int j = 0; j < 8; j++) {
        acc[j] += __shfl_xor_sync(0xffffffffu, acc[j], 8);
        acc[j] += __shfl_xor_sync(0xffffffffu, acc[j], 16);
    }
    wsum += __shfl_xor_sync(0xffffffffu, wsum, 8);
    wsum += __shfl_xor_sync(0xffffffffu, wsum, 16);

    if (eg == 0) {
        float inv = 1.0f / (wsum + 1e-15f);
        float o[8];
#pragma unroll
        for (int j = 0; j < 8; j++) {
            float hp = acc[j] * inv;
            o[j] = hp > 0.0f ? hp : expm1f(hp);
        }
        float* dst = out + (size_t)node * F_OUT + sub * 8;
        *(float4*)(dst)     = make_float4(o[0], o[1], o[2], o[3]);
        *(float4*)(dst + 4) = make_float4(o[4], o[5], o[6], o[7]);
    }
}

// ---------------------------------------------------------------------------
extern "C" void kernel_launch(void* const* d_in, const int* in_sizes, int n_in,
                              void* d_out, int out_size) {
    // Identify inputs by element count (robust to metadata ordering)
    int idx[4] = {0, 1, 2, 3};
    for (int i = 1; i < 4 && i < n_in; i++) {
        int k = idx[i], j = i - 1;
        while (j >= 0 && in_sizes[idx[j]] < in_sizes[k]) { idx[j + 1] = idx[j]; j--; }
        idx[j + 1] = k;
    }
    const float* X    = (const float*)d_in[idx[0]];
    const int*   ei32 = (const int*)d_in[idx[1]];
    const float* W    = (const float*)d_in[idx[2]];
    const float* a    = (const float*)d_in[idx[3]];
    float*       out  = (float*)d_out;

    int M = in_sizes[idx[0]] / F_IN;   // 100000
    int E = in_sizes[idx[1]] / 2;      // 3200000

    cudaFuncSetAttribute(gemm_kernel,
                         cudaFuncAttributeMaxDynamicSharedMemorySize, SMEM_GEMM);

    // Fork-join graph: branch A (default stream) = gemm;
    // branch B (s2) = rank -> scan -> scatter. Join before aggregate.
    cudaStream_t s2;
    cudaStreamCreateWithFlags(&s2, cudaStreamNonBlocking);
    cudaEvent_t evFork, evJoin;
    cudaEventCreateWithFlags(&evFork, cudaEventDisableTiming);
    cudaEventCreateWithFlags(&evJoin, cudaEventDisableTiming);

    init_kernel<<<(M + 511) / 512, 512>>>(ei32, M);
    cudaEventRecord(evFork, 0);
    cudaStreamWaitEvent(s2, evFork, 0);

    // Branch B on s2: edge pipeline (independent of gemm outputs)
    rank_kernel<<<(E + 255) / 256, 256, 0, s2>>>(ei32, E, M);
    int nblk = (M + 1023) / 1024;
    scan_kernel<<<nblk, 1024, 0, s2>>>(M, nblk);
    scatter_kernel<<<(E + 255) / 256, 256, 0, s2>>>(ei32, E, M);
    cudaEventRecord(evJoin, s2);

    // Branch A on default stream: gemm + fused s1/s2 (cp.async double-buffer)
    gemm_kernel<<<(M + 127) / 128, 256, SMEM_GEMM>>>(X, W, a, M);

    // Join, then aggregate
    cudaStreamWaitEvent(0, evJoin, 0);
    aggregate_kernel<<<(M * 32 + 255) / 256, 256>>>(out, M);

    cudaEventDestroy(evFork);
    cudaEventDestroy(evJoin);
    cudaStreamDestroy(s2);
}